// round 11
// baseline (speedup 1.0000x reference)
#include <cuda_runtime.h>
#include <cuda_fp16.h>
#include <cstdint>

#define NSEQ   8192
#define DH     64
#define BR     128
#define BC     64
#define NT     256
#define NTILES (NSEQ / BC)
#define LOG2E  1.4426950408889634f

// ---- smem layout (bytes) ----
// Qf: 8 warps x 4 units x 32 lanes x 16B = 16KB fp16 A-frags
// stage s: Kh [64 m][72 halves] (9216B) + Vh [72 n][72 halves] (10368B)
//   strides 144B = 16 mod 128 -> B-frag lds.32 conflict-free
//   Vh rows 64..71 = ones-block (row 64 = 1.0) -> l via MMA
#define QF_OFF   0
#define STG_OFF  16384
#define KH_BYTES (64 * 144)
#define VH_BYTES (72 * 144)
#define STG_BYTES (KH_BYTES + VH_BYTES)          // 19584
#define KH_OFF(s) (STG_OFF + (s) * STG_BYTES)
#define VH_OFF(s) (KH_OFF(s) + KH_BYTES)
#define OSTR     66
#define WS_OFF   33792                           // right after Os (128*66*4)
#define SMEM_TOTAL (STG_OFF + 2 * STG_BYTES)     // 55552

typedef unsigned long long u64;

__device__ __half g_xh [4 * DH * NSEQ];   // [b][f][n]  (m-contiguous)  4MB
__device__ __half g_xhT[4 * NSEQ * DH];   // [b][n][f]  (f-contiguous)  4MB
__device__ float  g_rq2[4][NSEQ];         // ||q_n||^2 of fp16-quantized q

// ---------------- helpers ----------------
__device__ __forceinline__ uint32_t smem_u32(const void* p) {
    uint32_t a;
    asm("{ .reg .u64 t; cvta.to.shared.u64 t, %1; cvt.u32.u64 %0, t; }" : "=r"(a) : "l"(p));
    return a;
}
// fp16 m16n8k16 mma, f32 accumulate (baseline PTX, sm_80+)
__device__ __forceinline__ void mma16(float* d, uint32_t a0, uint32_t a1, uint32_t a2,
                                      uint32_t a3, uint32_t b0, uint32_t b1) {
    asm volatile("mma.sync.aligned.m16n8k16.row.col.f32.f16.f16.f32 "
        "{%0,%1,%2,%3}, {%4,%5,%6,%7}, {%8,%9}, {%0,%1,%2,%3};"
        : "+f"(d[0]), "+f"(d[1]), "+f"(d[2]), "+f"(d[3])
        : "r"(a0), "r"(a1), "r"(a2), "r"(a3), "r"(b0), "r"(b1));
}
// pack two f32 -> half2 (lo=f0), then 2-wide exp2 on the MUFU
__device__ __forceinline__ uint32_t exp2h2(float f0, float f1) {
    uint32_t h, r;
    asm("cvt.rn.f16x2.f32 %0, %1, %2;" : "=r"(h) : "f"(f1), "f"(f0));   // first src -> hi
    asm("ex2.approx.f16x2 %0, %1;" : "=r"(r) : "r"(h));
    return r;
}
__device__ __forceinline__ void cpasync16(uint32_t dst, const void* src) {
    asm volatile("cp.async.ca.shared.global [%0], [%1], 16;" :: "r"(dst), "l"(src));
}
#define CP_COMMIT()  asm volatile("cp.async.commit_group;" ::: "memory")
#define CP_WAIT(n)   asm volatile("cp.async.wait_group %0;" :: "n"(n) : "memory")

// packed f32x2 for the W epilogue
__device__ __forceinline__ u64 dup2f(float x) {
    u64 r; asm("mov.b64 %0, {%1, %1};" : "=l"(r) : "f"(x)); return r;
}
__device__ __forceinline__ void unpack2f(u64 v, float& lo, float& hi) {
    asm("mov.b64 {%0, %1}, %2;" : "=f"(lo), "=f"(hi) : "l"(v));
}
__device__ __forceinline__ void fma2(u64& d, u64 a, u64 b) {
    asm("fma.rn.f32x2 %0, %1, %2, %0;" : "+l"(d) : "l"(a), "l"(b));
}

// ---- pre-pass: fp16-quantize x into both layouts + per-row squared norms ----
__global__ void prep_kernel(const float* __restrict__ x) {
    int b = blockIdx.y;
    int n = blockIdx.x * 256 + threadIdx.x;
    const float* xb = x + b * DH * NSEQ;
    __half* xh  = g_xh  + b * DH * NSEQ;
    __half* xhT = g_xhT + b * NSEQ * DH;
    float s = 0.0f;
    #pragma unroll
    for (int f = 0; f < DH; ++f) {
        float v = xb[f * NSEQ + n];
        __half h = __float2half_rn(v);
        float vq = __half2float(h);
        xh[f * NSEQ + n]  = h;
        xhT[n * DH + f]   = h;
        s = fmaf(vq, vq, s);
    }
    g_rq2[b][n] = s;
}

// ---------------- main fused kernel ----------------
// 8 warps; warp wp owns rows [row0 + wp*16, +16): D-frag rows g and g+8.
__global__ void __launch_bounds__(NT, 2) fa_h16_kernel(const float* __restrict__ w,
                                                       float* __restrict__ out) {
    extern __shared__ char smem[];
    const uint32_t sb = smem_u32(smem);

    const int t   = threadIdx.x;
    const int wp  = t >> 5;
    const int l   = t & 31;
    const int g   = l >> 2;
    const int tig = l & 3;
    const int b    = blockIdx.y;
    const int row0 = blockIdx.x * BR;
    const __half* xh  = g_xh  + b * DH * NSEQ;
    const __half* xhT = g_xhT + b * NSEQ * DH;

    // ---- Q fp16 A-frags: gather once from xhT, store frag-major ----
    {
        const int i0 = row0 + wp * 16 + g;
        #pragma unroll
        for (int kt = 0; kt < 4; ++kt) {
            uint32_t a0 = *(const uint32_t*)(xhT + (size_t)i0 * DH + 16 * kt + 2 * tig);
            uint32_t a1 = *(const uint32_t*)(xhT + (size_t)(i0 + 8) * DH + 16 * kt + 2 * tig);
            uint32_t a2 = *(const uint32_t*)(xhT + (size_t)i0 * DH + 16 * kt + 2 * tig + 8);
            uint32_t a3 = *(const uint32_t*)(xhT + (size_t)(i0 + 8) * DH + 16 * kt + 2 * tig + 8);
            *(uint4*)(smem + QF_OFF + ((wp * 4 + kt) * 32 + l) * 16) =
                make_uint4(a0, a1, a2, a3);
        }
    }

    // ---- ones-block rows of both Vh buffers (rows 64..71; row 64 = 1.0) ----
    #pragma unroll
    for (int i = t; i < 2 * 8 * 64; i += NT) {
        int bufi = i >> 9, rr = (i >> 6) & 7, cc = i & 63;
        *(__half*)(smem + VH_OFF(bufi) + (64 + rr) * 144 + cc * 2) =
            __float2half(rr == 0 ? 1.0f : 0.0f);
    }

    // diagonal softmax shift (exact, per-row): m = ||q||^2; store -m*log2e
    float m2n[2];
    {
        int r1 = row0 + wp * 16 + g;
        m2n[0] = -g_rq2[b][r1]     * LOG2E;
        m2n[1] = -g_rq2[b][r1 + 8] * LOG2E;
    }

    float Oa[8][4], Ol[4];
    #pragma unroll
    for (int j = 0; j < 8; ++j)
        #pragma unroll
        for (int r = 0; r < 4; ++r) Oa[j][r] = 0.0f;
    #pragma unroll
    for (int r = 0; r < 4; ++r) Ol[r] = 0.0f;

    // ---- prologue: issue tile 0 into buf 0 (each thread 2 K + 2 V chunks) ----
    #pragma unroll
    for (int k = 0; k < 2; ++k) {
        int ci = k * NT + t, r = ci >> 3, c = ci & 7;
        cpasync16(sb + KH_OFF(0) + r * 144 + c * 16, xhT + (size_t)r * DH + c * 8);
        cpasync16(sb + VH_OFF(0) + r * 144 + c * 16, xh + (size_t)r * NSEQ + c * 8);
    }
    CP_COMMIT();
    __syncthreads();

    for (int ct = 0; ct < NTILES; ++ct) {
        const int buf = ct & 1;

        // issue next tile into buf^1 (wraps harmlessly on last iter)
        {
            const int mn = ((ct + 1) & (NTILES - 1)) * BC;
            #pragma unroll
            for (int k = 0; k < 2; ++k) {
                int ci = k * NT + t, r = ci >> 3, c = ci & 7;
                cpasync16(sb + KH_OFF(buf ^ 1) + r * 144 + c * 16,
                          xhT + (size_t)(mn + r) * DH + c * 8);
                cpasync16(sb + VH_OFF(buf ^ 1) + r * 144 + c * 16,
                          xh + (size_t)r * NSEQ + mn + c * 8);
            }
            CP_COMMIT();
        }
        CP_WAIT(1);
        __syncthreads();

        const char* khp = smem + KH_OFF(buf);
        const char* vhp = smem + VH_OFF(buf);

        // ---- S = Q . K^T  (32 MMAs/warp) ----
        float Sa[8][4];
        #pragma unroll
        for (int j = 0; j < 8; ++j)
            #pragma unroll
            for (int r = 0; r < 4; ++r) Sa[j][r] = 0.0f;

        #pragma unroll
        for (int kt = 0; kt < 4; ++kt) {
            uint4 aq = *(const uint4*)(smem + QF_OFF + ((wp * 4 + kt) * 32 + l) * 16);
            #pragma unroll
            for (int j = 0; j < 8; ++j) {
                const char* kba = khp + (8 * j + g) * 144 + (16 * kt + 2 * tig) * 2;
                uint32_t b0 = *(const uint32_t*)kba;
                uint32_t b1 = *(const uint32_t*)(kba + 16);
                mma16(Sa[j], aq.x, aq.y, aq.z, aq.w, b0, b1);
            }
        }

        // ---- softmax: p = fp16(exp2(s*log2e - ||q||^2*log2e)); D-frag pairs ARE
        //      the fp16 A-frag half2s for the V-GEMM ----
        uint32_t ph0[8], ph1[8];
        #pragma unroll
        for (int j = 0; j < 8; ++j) {
            float f0 = fmaf(Sa[j][0], LOG2E, m2n[0]);
            float f1 = fmaf(Sa[j][1], LOG2E, m2n[0]);
            float f2 = fmaf(Sa[j][2], LOG2E, m2n[1]);
            float f3 = fmaf(Sa[j][3], LOG2E, m2n[1]);
            ph0[j] = exp2h2(f0, f1);
            ph1[j] = exp2h2(f2, f3);
        }

        // ---- O += P . V ; 9th n-block (ones) accumulates l in f32 (36 MMAs) ----
        #pragma unroll
        for (int kt = 0; kt < 4; ++kt) {
            #pragma unroll
            for (int j = 0; j < 9; ++j) {
                const char* vba = vhp + (8 * j + g) * 144 + (16 * kt + 2 * tig) * 2;
                uint32_t b0 = *(const uint32_t*)vba;
                uint32_t b1 = *(const uint32_t*)(vba + 16);
                float* d = (j < 8) ? Oa[j] : Ol;
                mma16(d, ph0[2 * kt], ph1[2 * kt], ph0[2 * kt + 1], ph1[2 * kt + 1],
                      b0, b1);
            }
        }
        __syncthreads();   // all reads of buf done before iter ct+1 overwrites it
    }

    CP_WAIT(0);
    __syncthreads();

    // ---- epilogue: l in Ol c0/c2 of tig=0 lanes; normalize, apply W ----
    float inv0, inv1;
    {
        float l0 = __shfl_sync(0xffffffffu, Ol[0], l & 28);
        float l1 = __shfl_sync(0xffffffffu, Ol[2], l & 28);
        inv0 = 1.0f / l0;
        inv1 = 1.0f / l1;
    }

    float* Os = (float*)smem;          // [128][66], aliases Qf + stage0 (dead)
    {
        int r1 = wp * 16 + g;
        #pragma unroll
        for (int j = 0; j < 8; ++j) {
            *(float2*)(Os + r1 * OSTR + 8 * j + 2 * tig) =
                make_float2(Oa[j][0] * inv0, Oa[j][1] * inv0);
            *(float2*)(Os + (r1 + 8) * OSTR + 8 * j + 2 * tig) =
                make_float2(Oa[j][2] * inv1, Oa[j][3] * inv1);
        }
    }
    float* Ws = (float*)(smem + WS_OFF);
    #pragma unroll
    for (int k = 0; k < (DH * DH) / NT; ++k) Ws[k * NT + t] = w[k * NT + t];
    __syncthreads();

    // W GEMV: thread t owns row i = t>>1, output half (t&1)*32
    const int i    = t >> 1;
    const int half = t & 1;
    u64 acc[16];
    #pragma unroll
    for (int k = 0; k < 16; ++k) acc[k] = 0ull;
    #pragma unroll 4
    for (int f = 0; f < DH; ++f) {
        u64 ad = dup2f(Os[i * OSTR + f]);
        const u64* wr = (const u64*)(Ws + f * DH + half * 32);
        #pragma unroll
        for (int op = 0; op < 16; ++op) fma2(acc[op], ad, wr[op]);
    }
    float* ob = out + b * DH * NSEQ + row0 + i;
    #pragma unroll
    for (int op = 0; op < 16; ++op) {
        float lo, hi;
        unpack2f(acc[op], lo, hi);
        ob[(half * 32 + 2 * op + 0) * NSEQ] = lo;
        ob[(half * 32 + 2 * op + 1) * NSEQ] = hi;
    }
}

extern "C" void kernel_launch(void* const* d_in, const int* in_sizes, int n_in,
                              void* d_out, int out_size) {
    const float* x = (const float*)d_in[0];   // [4, 64, 8192] f32
    const float* w = (const float*)d_in[1];   // [64, 64] f32
    float* out = (float*)d_out;               // [4, 64, 8192] f32

    prep_kernel<<<dim3(NSEQ / 256, 4), 256>>>(x);

    cudaFuncSetAttribute(fa_h16_kernel, cudaFuncAttributeMaxDynamicSharedMemorySize,
                         SMEM_TOTAL);
    fa_h16_kernel<<<dim3(NSEQ / BR, 4), NT, SMEM_TOTAL>>>(w, out);
}

// round 12
// speedup vs baseline: 1.3108x; 1.3108x over previous
#include <cuda_runtime.h>
#include <cuda_fp16.h>
#include <cstdint>

#define NSEQ   8192
#define DH     64
#define BR     128
#define BC     64
#define NT     128
#define NTILES (NSEQ / BC)
#define LOG2E  1.4426950408889634f

// ---- smem layout (bytes) ----
// stage s: Kh [64 m][72 halves] (9216B) + Vh [64 n][72 halves] (9216B)
//   stride 144B: successive rows shift 16B -> ldmatrix 8-row reads conflict-free
// epilogue: Os [128][66] floats (33792B) then Ws (16KB), aliasing dead stages
#define KH_BYTES (64 * 144)
#define VH_BYTES (64 * 144)
#define STG_BYTES (KH_BYTES + VH_BYTES)          // 18432
#define KH_OFF(s) ((s) * STG_BYTES)
#define VH_OFF(s) (KH_OFF(s) + KH_BYTES)
#define OSTR     66
#define WS_OFF   33792
#define SMEM_TOTAL 50176                         // max(2*18432, 33792+16384)

#define ONES_H2  0x3C003C00u                     // half2(1.0, 1.0)

typedef unsigned long long u64;

__device__ __half g_xh [4 * DH * NSEQ];   // [b][f][n]  (m-contiguous)  4MB
__device__ __half g_xhT[4 * NSEQ * DH];   // [b][n][f]  (f-contiguous)  4MB
__device__ float  g_rq2[4][NSEQ];         // ||q_n||^2 of fp16-quantized q

// ---------------- helpers ----------------
__device__ __forceinline__ uint32_t smem_u32(const void* p) {
    uint32_t a;
    asm("{ .reg .u64 t; cvta.to.shared.u64 t, %1; cvt.u32.u64 %0, t; }" : "=r"(a) : "l"(p));
    return a;
}
// fp16 m16n8k16 mma, f32 accumulate (baseline PTX, sm_80+)
__device__ __forceinline__ void mma16(float* d, uint32_t a0, uint32_t a1, uint32_t a2,
                                      uint32_t a3, uint32_t b0, uint32_t b1) {
    asm volatile("mma.sync.aligned.m16n8k16.row.col.f32.f16.f16.f32 "
        "{%0,%1,%2,%3}, {%4,%5,%6,%7}, {%8,%9}, {%0,%1,%2,%3};"
        : "+f"(d[0]), "+f"(d[1]), "+f"(d[2]), "+f"(d[3])
        : "r"(a0), "r"(a1), "r"(a2), "r"(a3), "r"(b0), "r"(b1));
}
// ldmatrix x4: rm = 8x8 b16 matrix m; lane l gets M[l>>2][2(l&3),2(l&3)+1] (B-frag layout)
__device__ __forceinline__ void ldsm4(uint32_t* r, uint32_t addr) {
    asm volatile("ldmatrix.sync.aligned.m8n8.x4.shared.b16 {%0,%1,%2,%3}, [%4];"
        : "=r"(r[0]), "=r"(r[1]), "=r"(r[2]), "=r"(r[3]) : "r"(addr));
}
// pack two f32 -> half2 (lo=f0), then 2-wide exp2 on the MUFU
__device__ __forceinline__ uint32_t exp2h2(float f0, float f1) {
    uint32_t h, r;
    asm("cvt.rn.f16x2.f32 %0, %1, %2;" : "=r"(h) : "f"(f1), "f"(f0));   // first src -> hi
    asm("ex2.approx.f16x2 %0, %1;" : "=r"(r) : "r"(h));
    return r;
}
__device__ __forceinline__ void cpasync16(uint32_t dst, const void* src) {
    asm volatile("cp.async.ca.shared.global [%0], [%1], 16;" :: "r"(dst), "l"(src));
}
#define CP_COMMIT()  asm volatile("cp.async.commit_group;" ::: "memory")
#define CP_WAIT(n)   asm volatile("cp.async.wait_group %0;" :: "n"(n) : "memory")

// packed f32x2 for the W epilogue
__device__ __forceinline__ u64 dup2f(float x) {
    u64 r; asm("mov.b64 %0, {%1, %1};" : "=l"(r) : "f"(x)); return r;
}
__device__ __forceinline__ void unpack2f(u64 v, float& lo, float& hi) {
    asm("mov.b64 {%0, %1}, %2;" : "=f"(lo), "=f"(hi) : "l"(v));
}
__device__ __forceinline__ void fma2(u64& d, u64 a, u64 b) {
    asm("fma.rn.f32x2 %0, %1, %2, %0;" : "+l"(d) : "l"(a), "l"(b));
}

// ---- pre-pass: fp16-quantize x into both layouts + per-row squared norms ----
__global__ void prep_kernel(const float* __restrict__ x) {
    int b = blockIdx.y;
    int n = blockIdx.x * 256 + threadIdx.x;
    const float* xb = x + b * DH * NSEQ;
    __half* xh  = g_xh  + b * DH * NSEQ;
    __half* xhT = g_xhT + b * NSEQ * DH;
    float s = 0.0f;
    #pragma unroll
    for (int f = 0; f < DH; ++f) {
        float v = xb[f * NSEQ + n];
        __half h = __float2half_rn(v);
        float vq = __half2float(h);
        xh[f * NSEQ + n]  = h;
        xhT[n * DH + f]   = h;
        s = fmaf(vq, vq, s);
    }
    g_rq2[b][n] = s;
}

// ---------------- main fused kernel ----------------
// 4 warps; warp wp owns rows [row0 + wp*32, +32) (mi = 0,1 -> 16 rows each).
__global__ void __launch_bounds__(NT, 2) fa_h16_kernel(const float* __restrict__ w,
                                                       float* __restrict__ out) {
    extern __shared__ char smem[];
    const uint32_t sb = smem_u32(smem);

    const int t   = threadIdx.x;
    const int wp  = t >> 5;
    const int l   = t & 31;
    const int g   = l >> 2;
    const int tig = l & 3;
    const int b    = blockIdx.y;
    const int row0 = blockIdx.x * BR;
    const __half* xh  = g_xh  + b * DH * NSEQ;
    const __half* xhT = g_xhT + b * NSEQ * DH;

    // ldmatrix per-lane offset: matrix m = l>>3 -> (j-sub = m>>1, k-half = m&1), row = l&7
    const uint32_t lmoff = (uint32_t)((8 * ((l >> 3) >> 1) + (l & 7)) * 144
                                      + ((l >> 3) & 1) * 16);

    // ---- Q fp16 A-frags: pinned in registers (loaded once from gmem) ----
    uint32_t aq[2][4][4];
    #pragma unroll
    for (int mi = 0; mi < 2; ++mi) {
        const int i0 = row0 + wp * 32 + mi * 16 + g;
        #pragma unroll
        for (int kt = 0; kt < 4; ++kt) {
            aq[mi][kt][0] = *(const uint32_t*)(xhT + (size_t)i0 * DH + 16 * kt + 2 * tig);
            aq[mi][kt][1] = *(const uint32_t*)(xhT + (size_t)(i0 + 8) * DH + 16 * kt + 2 * tig);
            aq[mi][kt][2] = *(const uint32_t*)(xhT + (size_t)i0 * DH + 16 * kt + 2 * tig + 8);
            aq[mi][kt][3] = *(const uint32_t*)(xhT + (size_t)(i0 + 8) * DH + 16 * kt + 2 * tig + 8);
        }
    }

    // ones-block B-frags are constants: row n=64+g of the virtual ones tile
    const uint32_t onesb = (g == 0) ? ONES_H2 : 0u;

    // diagonal softmax shift (exact, per-row): m = ||q||^2; store -m*log2e
    float m2n[2][2];
    #pragma unroll
    for (int mi = 0; mi < 2; ++mi) {
        int r1 = row0 + wp * 32 + mi * 16 + g;
        m2n[mi][0] = -g_rq2[b][r1]     * LOG2E;
        m2n[mi][1] = -g_rq2[b][r1 + 8] * LOG2E;
    }

    float Oa[2][8][4], Ol[2][4];
    #pragma unroll
    for (int mi = 0; mi < 2; ++mi) {
        #pragma unroll
        for (int j = 0; j < 8; ++j)
            #pragma unroll
            for (int r = 0; r < 4; ++r) Oa[mi][j][r] = 0.0f;
        #pragma unroll
        for (int r = 0; r < 4; ++r) Ol[mi][r] = 0.0f;
    }

    // ---- prologue: issue tile 0 into buf 0 (1024 16B chunks, 8 per thread) ----
    #pragma unroll
    for (int k = 0; k < 4; ++k) {
        int ci = k * NT + t, r = ci >> 3, c = ci & 7;
        cpasync16(sb + KH_OFF(0) + r * 144 + c * 16, xhT + (size_t)r * DH + c * 8);
        cpasync16(sb + VH_OFF(0) + r * 144 + c * 16, xh + (size_t)r * NSEQ + c * 8);
    }
    CP_COMMIT();
    __syncthreads();

    for (int ct = 0; ct < NTILES; ++ct) {
        const int buf = ct & 1;

        // issue next tile into buf^1 (wraps harmlessly on last iter)
        {
            const int mn = ((ct + 1) & (NTILES - 1)) * BC;
            #pragma unroll
            for (int k = 0; k < 4; ++k) {
                int ci = k * NT + t, r = ci >> 3, c = ci & 7;
                cpasync16(sb + KH_OFF(buf ^ 1) + r * 144 + c * 16,
                          xhT + (size_t)(mn + r) * DH + c * 8);
                cpasync16(sb + VH_OFF(buf ^ 1) + r * 144 + c * 16,
                          xh + (size_t)r * NSEQ + mn + c * 8);
            }
            CP_COMMIT();
        }
        CP_WAIT(1);
        __syncthreads();

        const uint32_t kbase = sb + KH_OFF(buf) + lmoff;
        const uint32_t vbase = sb + VH_OFF(buf) + lmoff;

        // ---- S = Q . K^T : ldmatrix.x4 feeds 2 j-blocks x (b0,b1) per load ----
        float Sa[2][8][4];
        #pragma unroll
        for (int mi = 0; mi < 2; ++mi)
            #pragma unroll
            for (int j = 0; j < 8; ++j)
                #pragma unroll
                for (int r = 0; r < 4; ++r) Sa[mi][j][r] = 0.0f;

        #pragma unroll
        for (int kt = 0; kt < 4; ++kt) {
            #pragma unroll
            for (int jp = 0; jp < 4; ++jp) {
                uint32_t bk[4];
                ldsm4(bk, kbase + jp * 2304 + kt * 32);
                mma16(Sa[0][2 * jp],     aq[0][kt][0], aq[0][kt][1], aq[0][kt][2],
                      aq[0][kt][3], bk[0], bk[1]);
                mma16(Sa[1][2 * jp],     aq[1][kt][0], aq[1][kt][1], aq[1][kt][2],
                      aq[1][kt][3], bk[0], bk[1]);
                mma16(Sa[0][2 * jp + 1], aq[0][kt][0], aq[0][kt][1], aq[0][kt][2],
                      aq[0][kt][3], bk[2], bk[3]);
                mma16(Sa[1][2 * jp + 1], aq[1][kt][0], aq[1][kt][1], aq[1][kt][2],
                      aq[1][kt][3], bk[2], bk[3]);
            }
        }

        // ---- softmax: p = fp16(exp2(s*log2e - ||q||^2*log2e)); D-frag pairs ARE
        //      the fp16 A-frag half2s for the V-GEMM ----
        uint32_t ph0[2][8], ph1[2][8];
        #pragma unroll
        for (int mi = 0; mi < 2; ++mi)
            #pragma unroll
            for (int j = 0; j < 8; ++j) {
                float f0 = fmaf(Sa[mi][j][0], LOG2E, m2n[mi][0]);
                float f1 = fmaf(Sa[mi][j][1], LOG2E, m2n[mi][0]);
                float f2 = fmaf(Sa[mi][j][2], LOG2E, m2n[mi][1]);
                float f3 = fmaf(Sa[mi][j][3], LOG2E, m2n[mi][1]);
                ph0[mi][j] = exp2h2(f0, f1);
                ph1[mi][j] = exp2h2(f2, f3);
            }

        // ---- O += P . V ; l accumulated via constant ones-frags ----
        #pragma unroll
        for (int kt = 0; kt < 4; ++kt) {
            #pragma unroll
            for (int jp = 0; jp < 4; ++jp) {
                uint32_t bv[4];
                ldsm4(bv, vbase + jp * 2304 + kt * 32);
                mma16(Oa[0][2 * jp],     ph0[0][2 * kt], ph1[0][2 * kt],
                      ph0[0][2 * kt + 1], ph1[0][2 * kt + 1], bv[0], bv[1]);
                mma16(Oa[1][2 * jp],     ph0[1][2 * kt], ph1[1][2 * kt],
                      ph0[1][2 * kt + 1], ph1[1][2 * kt + 1], bv[0], bv[1]);
                mma16(Oa[0][2 * jp + 1], ph0[0][2 * kt], ph1[0][2 * kt],
                      ph0[0][2 * kt + 1], ph1[0][2 * kt + 1], bv[2], bv[3]);
                mma16(Oa[1][2 * jp + 1], ph0[1][2 * kt], ph1[1][2 * kt],
                      ph0[1][2 * kt + 1], ph1[1][2 * kt + 1], bv[2], bv[3]);
            }
            mma16(Ol[0], ph0[0][2 * kt], ph1[0][2 * kt], ph0[0][2 * kt + 1],
                  ph1[0][2 * kt + 1], onesb, onesb);
            mma16(Ol[1], ph0[1][2 * kt], ph1[1][2 * kt], ph0[1][2 * kt + 1],
                  ph1[1][2 * kt + 1], onesb, onesb);
        }
        __syncthreads();   // all reads of buf done before iter ct+1 overwrites it
    }

    CP_WAIT(0);
    __syncthreads();

    // ---- epilogue: l in Ol c0/c2 of tig=0 lanes; normalize, apply W ----
    float inv[2][2];
    #pragma unroll
    for (int mi = 0; mi < 2; ++mi) {
        float l0 = __shfl_sync(0xffffffffu, Ol[mi][0], l & 28);
        float l1 = __shfl_sync(0xffffffffu, Ol[mi][2], l & 28);
        inv[mi][0] = 1.0f / l0;
        inv[mi][1] = 1.0f / l1;
    }

    float* Os = (float*)smem;          // [128][66], aliases dead stage buffers
    #pragma unroll
    for (int mi = 0; mi < 2; ++mi) {
        int r1 = wp * 32 + mi * 16 + g;
        #pragma unroll
        for (int j = 0; j < 8; ++j) {
            *(float2*)(Os + r1 * OSTR + 8 * j + 2 * tig) =
                make_float2(Oa[mi][j][0] * inv[mi][0], Oa[mi][j][1] * inv[mi][0]);
            *(float2*)(Os + (r1 + 8) * OSTR + 8 * j + 2 * tig) =
                make_float2(Oa[mi][j][2] * inv[mi][1], Oa[mi][j][3] * inv[mi][1]);
        }
    }
    float* Ws = (float*)(smem + WS_OFF);
    #pragma unroll
    for (int k = 0; k < (DH * DH) / NT; ++k) Ws[k * NT + t] = w[k * NT + t];
    __syncthreads();

    // thread t owns output row i = t; f32x2 GEMV against W
    u64 acc[32];
    #pragma unroll
    for (int i = 0; i < 32; ++i) acc[i] = 0ull;
    #pragma unroll 4
    for (int f = 0; f < DH; ++f) {
        u64 ad = dup2f(Os[t * OSTR + f]);
        const u64* wr = (const u64*)(Ws + f * DH);
        #pragma unroll
        for (int op = 0; op < 32; ++op) fma2(acc[op], ad, wr[op]);
    }
    float* ob = out + b * DH * NSEQ + row0 + t;
    #pragma unroll
    for (int op = 0; op < 32; ++op) {
        float lo, hi;
        unpack2f(acc[op], lo, hi);
        ob[(2 * op + 0) * NSEQ] = lo;
        ob[(2 * op + 1) * NSEQ] = hi;
    }
}

extern "C" void kernel_launch(void* const* d_in, const int* in_sizes, int n_in,
                              void* d_out, int out_size) {
    const float* x = (const float*)d_in[0];   // [4, 64, 8192] f32
    const float* w = (const float*)d_in[1];   // [64, 64] f32
    float* out = (float*)d_out;               // [4, 64, 8192] f32

    prep_kernel<<<dim3(NSEQ / 256, 4), 256>>>(x);

    cudaFuncSetAttribute(fa_h16_kernel, cudaFuncAttributeMaxDynamicSharedMemorySize,
                         SMEM_TOTAL);
    fa_h16_kernel<<<dim3(NSEQ / BR, 4), NT, SMEM_TOTAL>>>(w, out);
}